// round 16
// baseline (speedup 1.0000x reference)
#include <cuda_runtime.h>
#include <cuda_fp16.h>
#include <math.h>
#include <stdint.h>

#define BATCH 64
#define SEQ   512
#define EMB   192
#define NHEAD 6
#define HD    32
#define MROWS (BATCH * SEQ)   // 32768

// -------- scratch (device globals) --------
__device__ float  g_x   [MROWS * EMB];     // pre-LN x, only for k_merge (last layer)
__device__ __half g_xn_h[MROWS * EMB];     // LN output (fp16) = GEMM operand + residual
__device__ __half g_big_h[MROWS * 768];
__device__ __half g_attn_h[MROWS * EMB];
__device__ __half g_inw_h[6 * 576 * EMB];
__device__ __half g_outw_h[6 * EMB * EMB];
__device__ __half g_w1_h[6 * 768 * EMB];
__device__ __half g_w2_h[6 * EMB * 768];

__device__ __forceinline__ uint32_t sm32(const void* p) {
    uint32_t a;
    asm("{ .reg .u64 t; cvta.to.shared.u64 t, %1; cvt.u32.u64 %0, t; }"
        : "=r"(a) : "l"(p));
    return a;
}
__device__ __forceinline__ uint32_t h2u(__half2 h) {
    return *reinterpret_cast<uint32_t*>(&h);
}
__device__ __forceinline__ void ldsm4(uint32_t& r0, uint32_t& r1,
                                      uint32_t& r2, uint32_t& r3, uint32_t a) {
    asm volatile("ldmatrix.sync.aligned.m8n8.x4.shared.b16 {%0,%1,%2,%3}, [%4];"
                 : "=r"(r0), "=r"(r1), "=r"(r2), "=r"(r3) : "r"(a));
}
__device__ __forceinline__ void mma_f16(float* c, const uint32_t* a,
                                        uint32_t b0, uint32_t b1) {
    asm volatile(
        "mma.sync.aligned.m16n8k16.row.col.f32.f16.f16.f32 "
        "{%0,%1,%2,%3}, {%4,%5,%6,%7}, {%8,%9}, {%0,%1,%2,%3};"
        : "+f"(c[0]), "+f"(c[1]), "+f"(c[2]), "+f"(c[3])
        : "r"(a[0]), "r"(a[1]), "r"(a[2]), "r"(a[3]), "r"(b0), "r"(b1));
}
__device__ __forceinline__ void cp16u(uint32_t* dstu, const void* src) {
    uint32_t d = sm32(dstu);
    asm volatile("cp.async.cg.shared.global [%0], [%1], 16;" :: "r"(d), "l"(src));
}

// ---- single fused fp32->fp16 weight conversion (one launch) ----
#define F2H_N1 331776
#define F2H_N2 110592
#define F2H_N3 442368
#define F2H_N4 442368
#define F2H_TOT (F2H_N1 + F2H_N2 + F2H_N3 + F2H_N4)
__global__ void k_f2h_all(const float* __restrict__ a, const float* __restrict__ b,
                          const float* __restrict__ c, const float* __restrict__ d,
                          __half* __restrict__ ah, __half* __restrict__ bh,
                          __half* __restrict__ ch, __half* __restrict__ dh) {
    int i = blockIdx.x * 256 + threadIdx.x;
    if (i < F2H_N1) {
        float2 v = ((const float2*)a)[i];
        ((__half2*)ah)[i] = __floats2half2_rn(v.x, v.y);
    } else if (i < F2H_N1 + F2H_N2) {
        int j = i - F2H_N1;
        float2 v = ((const float2*)b)[j];
        ((__half2*)bh)[j] = __floats2half2_rn(v.x, v.y);
    } else if (i < F2H_N1 + F2H_N2 + F2H_N3) {
        int j = i - F2H_N1 - F2H_N2;
        float2 v = ((const float2*)c)[j];
        ((__half2*)ch)[j] = __floats2half2_rn(v.x, v.y);
    } else if (i < F2H_TOT) {
        int j = i - F2H_N1 - F2H_N2 - F2H_N3;
        float2 v = ((const float2*)d)[j];
        ((__half2*)dh)[j] = __floats2half2_rn(v.x, v.y);
    }
}

// ---------------------------------------------------------------
// Fused input transpose + LN1(layer 0). fp16 output only.
// ---------------------------------------------------------------
#define TIN_SMEM_B (192 * 65 * 4)
__global__ __launch_bounds__(256) void k_tin_ln(
    const float* __restrict__ img,
    const float* __restrict__ gam, const float* __restrict__ bet,
    __half* __restrict__ XNh) {
    extern __shared__ float ts[];
    int b = blockIdx.x >> 3, h = blockIdx.x & 7;
    int tid = threadIdx.x;
    const float* ib = img + ((size_t)b * EMB * 8 + h) * 64;
#pragma unroll
    for (int i = 0; i < 48; i++) {
        int idx = tid + i * 256;
        int c = idx >> 6, w = idx & 63;
        ts[c * 65 + w] = ib[(size_t)c * 512 + w];
    }
    __syncthreads();

    int row = tid >> 2, seg = tid & 3;
    float v[48];
    float s = 0.f, sq = 0.f;
#pragma unroll
    for (int j = 0; j < 48; j++) {
        float x = ts[(seg * 48 + j) * 65 + row];
        v[j] = x;
        s += x; sq += x * x;
    }
    s  += __shfl_xor_sync(0xffffffffu, s, 1);
    s  += __shfl_xor_sync(0xffffffffu, s, 2);
    sq += __shfl_xor_sync(0xffffffffu, sq, 1);
    sq += __shfl_xor_sync(0xffffffffu, sq, 2);
    float mu = s * (1.f / 192.f);
    float var = sq * (1.f / 192.f) - mu * mu;
    float rstd = rsqrtf(var + 1e-5f);

    int t = row * 8 + h;
    __half* xnh = XNh + ((size_t)b * SEQ + t) * EMB + seg * 48;
#pragma unroll
    for (int i = 0; i < 12; i++) {
        float4 g4 = *(const float4*)(gam + seg * 48 + i * 4);
        float4 b4 = *(const float4*)(bet + seg * 48 + i * 4);
        float nx = (v[i*4+0] - mu) * rstd * g4.x + b4.x;
        float ny = (v[i*4+1] - mu) * rstd * g4.y + b4.y;
        float nz = (v[i*4+2] - mu) * rstd * g4.z + b4.z;
        float nw = (v[i*4+3] - mu) * rstd * g4.w + b4.w;
        *(__half2*)(xnh + i * 4)     = __floats2half2_rn(nx, ny);
        *(__half2*)(xnh + i * 4 + 2) = __floats2half2_rn(nz, nw);
    }
}

// ---------------------------------------------------------------
// fp16 GEMM with ldmatrix fragments (best config):
// BM=128, BN=64, BK=32; 256 thr (8 warps 4x2); warp tile 32x32; 2 CTAs/SM.
// SCALEQ: scale q-columns (bn<192) by (1/sqrt(32))*log2e for exp2 softmax.
// ---------------------------------------------------------------
#define HPITCH 20
#define HSTAGE_U (128 * HPITCH + 64 * HPITCH)
#define GSMEM_BYTES (3 * HSTAGE_U * 4)

template <int RELU, int SCALEQ, int KT>
__global__ __launch_bounds__(256, 2) void k_gemm_h(
    const __half* __restrict__ A, const __half* __restrict__ W,
    const float* __restrict__ bias, __half* __restrict__ C, int Ntot) {
    extern __shared__ uint32_t shu[];
    const int K = KT * 32;

    const int bm = blockIdx.y * 128;
    const int bn = blockIdx.x * 64;
    const int tid = threadIdx.x;
    const int wid = tid >> 5;
    const int lane = tid & 31;
    const int wm = wid >> 1;
    const int wn = wid & 1;
    const int g  = lane >> 2;
    const int tg = lane & 3;
    const int lrow = lane & 15;
    const int lcol = (lane >> 4) * 4;

    const uint32_t shb = sm32(shu);

    auto load_stage = [&](int kt, int s) {
        uint32_t* as = shu + s * HSTAGE_U;
        uint32_t* bs = as + 128 * HPITCH;
        const __half* Ab = A + (size_t)bm * K + kt * 32;
        const __half* Wb = W + (size_t)bn * K + kt * 32;
#pragma unroll
        for (int i = 0; i < 2; i++) {
            int id = tid + i * 256;
            int r = id >> 2, c = id & 3;
            cp16u(as + r * HPITCH + c * 4, Ab + (size_t)r * K + c * 8);
        }
        {
            int r = tid >> 2, c = tid & 3;
            cp16u(bs + r * HPITCH + c * 4, Wb + (size_t)r * K + c * 8);
        }
        asm volatile("cp.async.commit_group;" ::: "memory");
    };

    float acc[2][4][4];
#pragma unroll
    for (int mm = 0; mm < 2; mm++)
#pragma unroll
        for (int nn = 0; nn < 4; nn++)
#pragma unroll
            for (int r = 0; r < 4; r++) acc[mm][nn][r] = 0.f;

    load_stage(0, 0);
    load_stage(1, 1);

#pragma unroll
    for (int kt = 0; kt < KT; kt++) {
        if (kt + 1 < KT) {
            asm volatile("cp.async.wait_group 1;" ::: "memory");
        } else {
            asm volatile("cp.async.wait_group 0;" ::: "memory");
        }
        __syncthreads();
        if (kt + 2 < KT) load_stage(kt + 2, (kt + 2) % 3);

        const uint32_t ab = shb + ((kt % 3) * HSTAGE_U) * 4;
        const uint32_t bb = ab + 128 * HPITCH * 4;
#pragma unroll
        for (int ks = 0; ks < 2; ks++) {
            uint32_t aa[2][4], bfr[4][2];
#pragma unroll
            for (int mm = 0; mm < 2; mm++)
                ldsm4(aa[mm][0], aa[mm][1], aa[mm][2], aa[mm][3],
                      ab + ((wm * 32 + mm * 16 + lrow) * HPITCH + ks * 8 + lcol) * 4);
#pragma unroll
            for (int np = 0; np < 2; np++) {
                uint32_t r0, r1, r2, r3;
                ldsm4(r0, r1, r2, r3,
                      bb + ((wn * 32 + np * 16 + lrow) * HPITCH + ks * 8 + lcol) * 4);
                bfr[np * 2][0] = r0; bfr[np * 2 + 1][0] = r1;
                bfr[np * 2][1] = r2; bfr[np * 2 + 1][1] = r3;
            }
#pragma unroll
            for (int mm = 0; mm < 2; mm++)
#pragma unroll
                for (int nn = 0; nn < 4; nn++)
                    mma_f16(acc[mm][nn], aa[mm], bfr[nn][0], bfr[nn][1]);
        }
    }

    // (1/sqrt(32)) * log2(e) so attention can use exp2 softmax directly
    const float scl = (SCALEQ && bn < 192) ? 0.25503508748672485f : 1.f;
#pragma unroll
    for (int mm = 0; mm < 2; mm++) {
#pragma unroll
        for (int half = 0; half < 2; half++) {
            int m = bm + wm * 32 + mm * 16 + g + half * 8;
            __half* crow = C + (size_t)m * Ntot + bn;
#pragma unroll
            for (int nn = 0; nn < 4; nn++) {
                int n = wn * 32 + nn * 8 + 2 * tg;
                float vx = (acc[mm][nn][half * 2 + 0] + bias[bn + n]) * scl;
                float vy = (acc[mm][nn][half * 2 + 1] + bias[bn + n + 1]) * scl;
                if (RELU) { vx = fmaxf(vx, 0.f); vy = fmaxf(vy, 0.f); }
                *(__half2*)(crow + n) = __floats2half2_rn(vx, vy);
            }
        }
    }
}

// ---------------------------------------------------------------
// fp16 GEMM (Ntot=192), BM=32 + fp16 residual + fused LN epilogue.
// 1024 CTAs (3.5 waves) to kill tail quantization. 8 warps (2x4),
// warp tile 16x48, acc[6][4].
// WRITEX=1 additionally stores pre-LN x (fp32) for k_merge (last layer).
// ---------------------------------------------------------------
#define LSTAGE_U (32 * HPITCH + 192 * HPITCH)   // 4480 u32 = 17920 B
#define LSMEM_BYTES (3 * LSTAGE_U * 4)          // 53760 B
#define XPITCH 196

template <int KT, int WRITEX>
__global__ __launch_bounds__(256, 2) void k_gemm_ln(
    const __half* __restrict__ A, const __half* __restrict__ W,
    const float* __restrict__ bias, const __half* __restrict__ R,
    const float* __restrict__ gam, const float* __restrict__ bet,
    float* __restrict__ X, __half* __restrict__ XNh) {
    extern __shared__ uint32_t shu[];
    const int K = KT * 32;

    const int bm = blockIdx.x * 32;
    const int tid = threadIdx.x;
    const int wid = tid >> 5;
    const int lane = tid & 31;
    const int wm = wid >> 2;          // 0..1 (16 rows each)
    const int wn = wid & 3;           // 0..3 (48 cols each)
    const int g  = lane >> 2;
    const int tg = lane & 3;
    const int lrow = lane & 15;
    const int lcol = (lane >> 4) * 4;

    const uint32_t shb = sm32(shu);

    auto load_stage = [&](int kt, int s) {
        uint32_t* as = shu + s * LSTAGE_U;
        uint32_t* bs = as + 32 * HPITCH;
        const __half* Ab = A + (size_t)bm * K + kt * 32;
        const __half* Wb = W + (size_t)kt * 32;
        if (tid < 128) {               // A: 32 rows x 4 chunks = 128
            int r = tid >> 2, c = tid & 3;
            cp16u(as + r * HPITCH + c * 4, Ab + (size_t)r * K + c * 8);
        }
#pragma unroll
        for (int i = 0; i < 3; i++) {  // B: 192 rows x 4 chunks = 768
            int id = tid + i * 256;
            int r = id >> 2, c = id & 3;
            cp16u(bs + r * HPITCH + c * 4, Wb + (size_t)r * K + c * 8);
        }
        asm volatile("cp.async.commit_group;" ::: "memory");
    };

    float acc[6][4];
#pragma unroll
    for (int nn = 0; nn < 6; nn++)
#pragma unroll
        for (int r = 0; r < 4; r++) acc[nn][r] = 0.f;

    load_stage(0, 0);
    load_stage(1, 1);

#pragma unroll
    for (int kt = 0; kt < KT; kt++) {
        if (kt + 1 < KT) {
            asm volatile("cp.async.wait_group 1;" ::: "memory");
        } else {
            asm volatile("cp.async.wait_group 0;" ::: "memory");
        }
        __syncthreads();
        if (kt + 2 < KT) load_stage(kt + 2, (kt + 2) % 3);

        const uint32_t ab = shb + ((kt % 3) * LSTAGE_U) * 4;
        const uint32_t bb = ab + 32 * HPITCH * 4;
#pragma unroll
        for (int ks = 0; ks < 2; ks++) {
            uint32_t aa[4], bfr[6][2];
            ldsm4(aa[0], aa[1], aa[2], aa[3],
                  ab + ((wm * 16 + lrow) * HPITCH + ks * 8 + lcol) * 4);
#pragma unroll
            for (int np = 0; np < 3; np++) {
                uint32_t r0, r1, r2, r3;
                ldsm4(r0, r1, r2, r3,
                      bb + ((wn * 48 + np * 16 + lrow) * HPITCH + ks * 8 + lcol) * 4);
                bfr[np * 2][0] = r0; bfr[np * 2 + 1][0] = r1;
                bfr[np * 2][1] = r2; bfr[np * 2 + 1][1] = r3;
            }
#pragma unroll
            for (int nn = 0; nn < 6; nn++)
                mma_f16(acc[nn], aa, bfr[nn][0], bfr[nn][1]);
        }
    }

    __syncthreads();
    float* xbuf = (float*)shu;   // [32][XPITCH] = 25088 B
#pragma unroll
    for (int half = 0; half < 2; half++) {
        int lr = wm * 16 + g + half * 8;
        const __half* rrow = R + (size_t)(bm + lr) * EMB;
#pragma unroll
        for (int nn = 0; nn < 6; nn++) {
            int n = wn * 48 + nn * 8 + 2 * tg;
            float2 r2 = __half22float2(*(const __half2*)(rrow + n));
            xbuf[lr * XPITCH + n]     = acc[nn][half * 2 + 0] + bias[n]     + r2.x;
            xbuf[lr * XPITCH + n + 1] = acc[nn][half * 2 + 1] + bias[n + 1] + r2.y;
        }
    }
    __syncthreads();

    // LN: 8 threads per row, 24 elems each
    {
        int row = tid >> 3, seg = tid & 7;
        const float* xr = xbuf + row * XPITCH + seg * 24;
        float s = 0.f, sq = 0.f;
        float v[24];
#pragma unroll
        for (int i = 0; i < 6; i++) {
            float4 x4 = *(const float4*)(xr + i * 4);
            v[i * 4 + 0] = x4.x; v[i * 4 + 1] = x4.y;
            v[i * 4 + 2] = x4.z; v[i * 4 + 3] = x4.w;
            s += x4.x + x4.y + x4.z + x4.w;
            sq += x4.x * x4.x + x4.y * x4.y + x4.z * x4.z + x4.w * x4.w;
        }
        s  += __shfl_xor_sync(0xffffffffu, s, 1);
        s  += __shfl_xor_sync(0xffffffffu, s, 2);
        s  += __shfl_xor_sync(0xffffffffu, s, 4);
        sq += __shfl_xor_sync(0xffffffffu, sq, 1);
        sq += __shfl_xor_sync(0xffffffffu, sq, 2);
        sq += __shfl_xor_sync(0xffffffffu, sq, 4);
        float mu = s * (1.f / 192.f);
        float var = sq * (1.f / 192.f) - mu * mu;
        float rstd = rsqrtf(var + 1e-5f);
        float* xo   = X   + (size_t)(bm + row) * EMB + seg * 24;
        __half* xnh = XNh + (size_t)(bm + row) * EMB + seg * 24;
#pragma unroll
        for (int i = 0; i < 6; i++) {
            float4 g4 = *(const float4*)(gam + seg * 24 + i * 4);
            float4 b4 = *(const float4*)(bet + seg * 24 + i * 4);
            float4 xv = { v[i*4+0], v[i*4+1], v[i*4+2], v[i*4+3] };
            if (WRITEX) *(float4*)(xo + i * 4) = xv;
            float nx = (xv.x - mu) * rstd * g4.x + b4.x;
            float ny = (xv.y - mu) * rstd * g4.y + b4.y;
            float nz = (xv.z - mu) * rstd * g4.z + b4.z;
            float nw = (xv.w - mu) * rstd * g4.w + b4.w;
            *(__half2*)(xnh + i * 4)     = __floats2half2_rn(nx, ny);
            *(__half2*)(xnh + i * 4 + 2) = __floats2half2_rn(nz, nw);
        }
    }
}

// ---------------------------------------------------------------
// Full-fp16 flash attention; q pre-scaled by (1/sqrt32)*log2e -> exp2 softmax.
// ---------------------------------------------------------------
#define QSU (128 * HPITCH)
#define KSU (64 * HPITCH)
#define VTU (32 * 36)
#define PBU (16 * 36)
#define ATTN_U (QSU + 2 * KSU + 2 * VTU + 8 * PBU)
#define ATTN_SMEM_B (ATTN_U * 4)

__global__ __launch_bounds__(256, 2) void k_attn_tc(
    const __half* __restrict__ qkv, __half* __restrict__ out, int local) {
    extern __shared__ uint32_t smu[];
    uint32_t* Qsu = smu;
    uint32_t* Ksu = Qsu + QSU;
    uint32_t* Vtu = Ksu + 2 * KSU;
    uint32_t* Pbu = Vtu + 2 * VTU;

    const int qt = blockIdx.x, hh = blockIdx.y, b = blockIdx.z;
    const int tid = threadIdx.x;
    const int wid = tid >> 5;
    const int lane = tid & 31;
    const int g = lane >> 2, tg = lane & 3;
    const int lrow = lane & 15;
    const int lcol = (lane >> 4) * 4;
    const __half* base = qkv + (size_t)b * SEQ * 576;

    const int ltok = tid >> 2, lpart = tid & 3;
    uint4 kf, vf;
    {
        const __half* row = base + (size_t)ltok * 576 + hh * HD + lpart * 8;
        kf = *(const uint4*)(row + EMB);
        vf = *(const uint4*)(row + 2 * EMB);
    }
#pragma unroll
    for (int i = 0; i < 2; i++) {
        int id = tid + i * 256;
        int tok = id >> 2, part = id & 3;
        uint4 qv = *(const uint4*)(base + (size_t)(qt * 128 + tok) * 576 + hh * HD + part * 8);
        *(uint4*)(Qsu + tok * HPITCH + part * 4) = qv;
    }
    {
        *(uint4*)(Ksu + ltok * HPITCH + lpart * 4) = kf;
        __half* vh = (__half*)Vtu;
        const __half* vsrc = (const __half*)&vf;
#pragma unroll
        for (int j = 0; j < 8; j++)
            vh[(lpart * 8 + j) * 72 + ltok] = vsrc[j];
    }
    __syncthreads();

    uint32_t qa[2][4];
    {
        uint32_t qb = sm32(Qsu);
#pragma unroll
        for (int c = 0; c < 2; c++)
            ldsm4(qa[c][0], qa[c][1], qa[c][2], qa[c][3],
                  qb + ((wid * 16 + lrow) * HPITCH + c * 8 + lcol) * 4);
    }

    float oacc[4][4];
#pragma unroll
    for (int nd = 0; nd < 4; nd++)
#pragma unroll
        for (int r = 0; r < 4; r++) oacc[nd][r] = 0.f;
    float m0 = -1e30f, m1 = -1e30f, l0 = 0.f, l1 = 0.f;

    const int qrow_grp = qt * 2 + (wid >= 4 ? 1 : 0);
    const int qw0 = (wid * 16 + g) & 63;
    const int qw1 = (wid * 16 + g + 8) & 63;
    uint32_t* Pw = Pbu + wid * PBU;
    const uint32_t pwb = sm32(Pw);

    for (int kt = 0; kt < 8; kt++) {
        int buf = kt & 1;
        if (kt < 7) {
            const __half* row = base + (size_t)((kt + 1) * 64 + ltok) * 576 + hh * HD + lpart * 8;
            kf = *(const uint4*)(row + EMB);
            vf = *(const uint4*)(row + 2 * EMB);
        }

        float sc[8][4];
#pragma unroll
        for (int n = 0; n < 8; n++)
#pragma unroll
            for (int r = 0; r < 4; r++) sc[n][r] = 0.f;
        {
            uint32_t kb = sm32(Ksu + buf * KSU);
#pragma unroll
            for (int c = 0; c < 2; c++) {
                uint32_t bfr[8][2];
#pragma unroll
                for (int np = 0; np < 4; np++) {
                    uint32_t r0, r1, r2, r3;
                    ldsm4(r0, r1, r2, r3,
                          kb + ((np * 16 + lrow) * HPITCH + c * 8 + lcol) * 4);
                    bfr[np * 2][0] = r0; bfr[np * 2 + 1][0] = r1;
                    bfr[np * 2][1] = r2; bfr[np * 2 + 1][1] = r3;
                }
#pragma unroll
                for (int n = 0; n < 8; n++)
                    mma_f16(sc[n], qa[c], bfr[n][0], bfr[n][1]);
            }
        }

        if (local) {
            int dr = qrow_grp - kt;
            if (dr <= 3 && dr >= -3) {
#pragma unroll
                for (int n = 0; n < 8; n++) {
#pragma unroll
                    for (int j = 0; j < 2; j++) {
                        int col = n * 8 + 2 * tg + j;
                        int d0 = qw0 - col, d1 = qw1 - col;
                        if (d0 <= 5 && d0 >= -5) sc[n][j] = -1e30f;
                        if (d1 <= 5 && d1 >= -5) sc[n][2 + j] = -1e30f;
                    }
                }
            }
        }

        float tm0 = sc[0][0], tm1 = sc[0][2];
#pragma unroll
        for (int n = 0; n < 8; n++) {
            tm0 = fmaxf(tm0, fmaxf(sc[n][0], sc[n][1]));
            tm1 = fmaxf(tm1, fmaxf(sc[n][2], sc[n][3]));
        }
        tm0 = fmaxf(tm0, __shfl_xor_sync(0xffffffffu, tm0, 1));
        tm0 = fmaxf(tm0, __shfl_xor_sync(0xffffffffu, tm0, 2));
        tm1 = fmaxf(tm1, __shfl_xor_sync(0xffffffffu, tm1, 1));
        tm1 = fmaxf(tm1, __shfl_xor_sync(0xffffffffu, tm1, 2));
        float nm0 = fmaxf(m0, tm0), nm1 = fmaxf(m1, tm1);
        float f0 = exp2f(m0 - nm0), f1 = exp2f(m1 - nm1);
        l0 *= f0; l1 *= f1;
#pragma unroll
        for (int nd = 0; nd < 4; nd++) {
            oacc[nd][0] *= f0; oacc[nd][1] *= f0;
            oacc[nd][2] *= f1; oacc[nd][3] *= f1;
        }
#pragma unroll
        for (int n = 0; n < 8; n++) {
            float p0 = exp2f(sc[n][0] - nm0);
            float p1 = exp2f(sc[n][1] - nm0);
            float p2 = exp2f(sc[n][2] - nm1);
            float p3 = exp2f(sc[n][3] - nm1);
            l0 += p0 + p1; l1 += p2 + p3;
            Pw[g * 36 + n * 4 + tg]       = h2u(__floats2half2_rn(p0, p1));
            Pw[(g + 8) * 36 + n * 4 + tg] = h2u(__floats2half2_rn(p2, p3));
        }
        m0 = nm0; m1 = nm1;
        __syncwarp();

        {
            uint32_t vb = sm32(Vtu + buf * VTU);
#pragma unroll
            for (int c = 0; c < 4; c++) {
                uint32_t pa[4];
                ldsm4(pa[0], pa[1], pa[2], pa[3],
                      pwb + (lrow * 36 + c * 8 + lcol) * 4);
                uint32_t vfr[4][2];
#pragma unroll
                for (int np = 0; np < 2; np++) {
                    uint32_t r0, r1, r2, r3;
                    ldsm4(r0, r1, r2, r3,
                          vb + ((np * 16 + lrow) * 36 + c * 8 + lcol) * 4);
                    vfr[np * 2][0] = r0; vfr[np * 2 + 1][0] = r1;
                    vfr[np * 2][1] = r2; vfr[np * 2 + 1][1] = r3;
                }
#pragma unroll
                for (int nd = 0; nd < 4; nd++)
                    mma_f16(oacc[nd], pa, vfr[nd][0], vfr[nd][1]);
            }
        }
        __syncwarp();

        if (kt < 7) {
            __syncthreads();
            int nbuf = buf ^ 1;
            *(uint4*)(Ksu + nbuf * KSU + ltok * HPITCH + lpart * 4) = kf;
            __half* vh = (__half*)(Vtu + nbuf * VTU);
            const __half* vsrc = (const __half*)&vf;
#pragma unroll
            for (int j = 0; j < 8; j++)
                vh[(lpart * 8 + j) * 72 + ltok] = vsrc[j];
            __syncthreads();
        }
    }

    l0 += __shfl_xor_sync(0xffffffffu, l0, 1);
    l0 += __shfl_xor_sync(0xffffffffu, l0, 2);
    l1 += __shfl_xor_sync(0xffffffffu, l1, 1);
    l1 += __shfl_xor_sync(0xffffffffu, l1, 2);
    float inv0 = 1.f / l0, inv1 = 1.f / l1;
    int r0 = qt * 128 + wid * 16 + g;
    __half* o0 = out + (size_t)(b * SEQ + r0) * EMB + hh * HD;
    __half* o1 = out + (size_t)(b * SEQ + r0 + 8) * EMB + hh * HD;
#pragma unroll
    for (int nd = 0; nd < 4; nd++) {
        int n = nd * 8 + 2 * tg;
        *(__half2*)(o0 + n) = __floats2half2_rn(oacc[nd][0] * inv0, oacc[nd][1] * inv0);
        *(__half2*)(o1 + n) = __floats2half2_rn(oacc[nd][2] * inv1, oacc[nd][3] * inv1);
    }
}

// ---------------------------------------------------------------
// Merge: conv (3,1) stride (2,1) pad (1,0) + channel LN (shuffle reduce).
// ---------------------------------------------------------------
__global__ __launch_bounds__(256) void k_merge(
    const float* __restrict__ cw, const float* __restrict__ cb,
    const float* __restrict__ mg, const float* __restrict__ mb,
    float* __restrict__ out) {
    int blk = blockIdx.x;
    int wg = blk & 15;
    int ho = (blk >> 4) & 3;
    int b  = blk >> 6;
    int co = threadIdx.x;
    int lane = co & 31, wrp = co >> 5;
    __shared__ float xs[4][3][EMB];
    __shared__ float red[8], red2[8];

    for (int idx = co; idx < 4 * 3 * EMB; idx += 256) {
        int g   = idx / (3 * EMB);
        int rem = idx - g * (3 * EMB);
        int kh  = rem / EMB;
        int ci  = rem - kh * EMB;
        int hh  = 2 * ho - 1 + kh;
        int w   = wg * 4 + g;
        float v = 0.f;
        if (hh >= 0 && hh < 8)
            v = g_x[((size_t)b * SEQ + (w * 8 + hh)) * EMB + ci];
        xs[g][kh][ci] = v;
    }
    __syncthreads();

    float bias = cb[co];
    float acc[4] = {bias, bias, bias, bias};
    const float* wp = cw + (size_t)co * (EMB * 3);
    for (int ci = 0; ci < EMB; ci++) {
        float w0 = wp[ci * 3 + 0], w1 = wp[ci * 3 + 1], w2 = wp[ci * 3 + 2];
#pragma unroll
        for (int g = 0; g < 4; g++)
            acc[g] += xs[g][0][ci] * w0 + xs[g][1][ci] * w1 + xs[g][2][ci] * w2;
    }

    float gm = mg[co], gb = mb[co];
#pragma unroll
    for (int g = 0; g < 4; g++) {
        float s = acc[g], sq = acc[g] * acc[g];
#pragma unroll
        for (int o = 16; o; o >>= 1) {
            s  += __shfl_xor_sync(0xffffffffu, s, o);
            sq += __shfl_xor_sync(0xffffffffu, sq, o);
        }
        if (lane == 0) { red[wrp] = s; red2[wrp] = sq; }
        __syncthreads();
        if (wrp == 0) {
            float a  = lane < 8 ? red[lane]  : 0.f;
            float b2 = lane < 8 ? red2[lane] : 0.f;
#pragma unroll
            for (int o = 4; o; o >>= 1) {
                a  += __shfl_xor_sync(0xffffffffu, a, o);
                b2 += __shfl_xor_sync(0xffffffffu, b2, o);
            }
            if (lane == 0) { red[0] = a; red2[0] = b2; }
        }
        __syncthreads();
        float mu = red[0] * (1.f / 256.f);
        float var = red2[0] * (1.f / 256.f) - mu * mu;
        float rstd = rsqrtf(var + 1e-5f);
        int w = wg * 4 + g;
        out[(((size_t)b * 256 + co) * 4 + ho) * 64 + w] = (acc[g] - mu) * rstd * gm + gb;
        __syncthreads();
    }
}

// ---------------------------------------------------------------
extern "C" void kernel_launch(void* const* d_in, const int* in_sizes, int n_in,
                              void* d_out, int out_size) {
    const float* image = (const float*)d_in[0];
    const float* in_w  = (const float*)d_in[1];
    const float* in_b  = (const float*)d_in[2];
    const float* out_w = (const float*)d_in[3];
    const float* out_b = (const float*)d_in[4];
    const float* ln1_g = (const float*)d_in[5];
    const float* ln1_b = (const float*)d_in[6];
    const float* ln2_g = (const float*)d_in[7];
    const float* ln2_b = (const float*)d_in[8];
    const float* w1    = (const float*)d_in[9];
    const float* b1    = (const float*)d_in[10];
    const float* w2    = (const float*)d_in[11];
    const float* b2    = (const float*)d_in[12];
    const float* convw = (const float*)d_in[13];
    const float* convb = (const float*)d_in[14];
    const float* mlng  = (const float*)d_in[15];
    const float* mlnb  = (const float*)d_in[16];

    float *px;
    __half *pxnh, *pbigh, *pattnh, *pinwh, *poutwh, *pw1h, *pw2h;
    cudaGetSymbolAddress((void**)&px,     g_x);
    cudaGetSymbolAddress((void**)&pxnh,   g_xn_h);
    cudaGetSymbolAddress((void**)&pbigh,  g_big_h);
    cudaGetSymbolAddress((void**)&pattnh, g_attn_h);
    cudaGetSymbolAddress((void**)&pinwh,  g_inw_h);
    cudaGetSymbolAddress((void**)&poutwh, g_outw_h);
    cudaGetSymbolAddress((void**)&pw1h,   g_w1_h);
    cudaGetSymbolAddress((void**)&pw2h,   g_w2_h);

    cudaFuncSetAttribute(k_gemm_h<0, 1, 6>, cudaFuncAttributeMaxDynamicSharedMemorySize, GSMEM_BYTES);
    cudaFuncSetAttribute(k_gemm_h<1, 0, 6>, cudaFuncAttributeMaxDynamicSharedMemorySize, GSMEM_BYTES);
    cudaFuncSetAttribute(k_gemm_ln<6, 0>,  cudaFuncAttributeMaxDynamicSharedMemorySize, LSMEM_BYTES);
    cudaFuncSetAttribute(k_gemm_ln<24, 0>, cudaFuncAttributeMaxDynamicSharedMemorySize, LSMEM_BYTES);
    cudaFuncSetAttribute(k_gemm_ln<24, 1>, cudaFuncAttributeMaxDynamicSharedMemorySize, LSMEM_BYTES);
    cudaFuncSetAttribute(k_attn_tc, cudaFuncAttributeMaxDynamicSharedMemorySize, ATTN_SMEM_B);
    cudaFuncSetAttribute(k_tin_ln,  cudaFuncAttributeMaxDynamicSharedMemorySize, TIN_SMEM_B);

    k_f2h_all<<<(F2H_TOT + 255) / 256, 256>>>(
        in_w, out_w, w1, w2, pinwh, poutwh, pw1h, pw2h);
    k_tin_ln<<<BATCH * 8, 256, TIN_SMEM_B>>>(image, ln1_g, ln1_b, pxnh);

    for (int l = 0; l < 6; l++) {
        int local = (l >= 2);  // LOCAL = (F, F, T, T, T, T)
        // qkv (q columns pre-scaled by (1/sqrt(hd))*log2e)
        k_gemm_h<0, 1, 6><<<dim3(9, MROWS / 128), 256, GSMEM_BYTES>>>(
            pxnh, pinwh + (size_t)l * 576 * EMB, in_b + l * 576, pbigh, 576);
        k_attn_tc<<<dim3(4, NHEAD, BATCH), 256, ATTN_SMEM_B>>>(pbigh, pattnh, local);
        // proj + fp16 residual + LN2
        k_gemm_ln<6, 0><<<MROWS / 32, 256, LSMEM_BYTES>>>(
            pattnh, poutwh + (size_t)l * EMB * EMB, out_b + l * EMB,
            pxnh, ln2_g + l * EMB, ln2_b + l * EMB, px, pxnh);
        k_gemm_h<1, 0, 6><<<dim3(12, MROWS / 128), 256, GSMEM_BYTES>>>(
            pxnh, pw1h + (size_t)l * 768 * EMB, b1 + l * 768, pbigh, 768);
        int ln = (l + 1) % 6;
        // mlp2 + fp16 residual + LN1_{l+1}; only last layer stores fp32 x for merge
        if (l == 5) {
            k_gemm_ln<24, 1><<<MROWS / 32, 256, LSMEM_BYTES>>>(
                pbigh, pw2h + (size_t)l * EMB * 768, b2 + l * EMB,
                pxnh, ln1_g + ln * EMB, ln1_b + ln * EMB, px, pxnh);
        } else {
            k_gemm_ln<24, 0><<<MROWS / 32, 256, LSMEM_BYTES>>>(
                pbigh, pw2h + (size_t)l * EMB * 768, b2 + l * EMB,
                pxnh, ln1_g + ln * EMB, ln1_b + ln * EMB, px, pxnh);
        }
    }

    k_merge<<<4096, 256>>>(convw, convb, mlng, mlnb, (float*)d_out);
}

// round 17
// speedup vs baseline: 1.0528x; 1.0528x over previous
#include <cuda_runtime.h>
#include <cuda_fp16.h>
#include <math.h>
#include <stdint.h>

#define BATCH 64
#define SEQ   512
#define EMB   192
#define NHEAD 6
#define HD    32
#define MROWS (BATCH * SEQ)   // 32768

// -------- scratch (device globals) --------
__device__ float  g_x   [MROWS * EMB];     // pre-LN x, only for k_merge (last layer)
__device__ __half g_xn_h[MROWS * EMB];     // LN output (fp16) = GEMM operand + residual
__device__ __half g_big_h[MROWS * 768];
__device__ __half g_attn_h[MROWS * EMB];
__device__ __half g_inw_h[6 * 576 * EMB];
__device__ __half g_outw_h[6 * EMB * EMB];
__device__ __half g_w1_h[6 * 768 * EMB];
__device__ __half g_w2_h[6 * EMB * 768];

__device__ __forceinline__ uint32_t sm32(const void* p) {
    uint32_t a;
    asm("{ .reg .u64 t; cvta.to.shared.u64 t, %1; cvt.u32.u64 %0, t; }"
        : "=r"(a) : "l"(p));
    return a;
}
__device__ __forceinline__ uint32_t h2u(__half2 h) {
    return *reinterpret_cast<uint32_t*>(&h);
}
__device__ __forceinline__ void ldsm4(uint32_t& r0, uint32_t& r1,
                                      uint32_t& r2, uint32_t& r3, uint32_t a) {
    asm volatile("ldmatrix.sync.aligned.m8n8.x4.shared.b16 {%0,%1,%2,%3}, [%4];"
                 : "=r"(r0), "=r"(r1), "=r"(r2), "=r"(r3) : "r"(a));
}
__device__ __forceinline__ void mma_f16(float* c, const uint32_t* a,
                                        uint32_t b0, uint32_t b1) {
    asm volatile(
        "mma.sync.aligned.m16n8k16.row.col.f32.f16.f16.f32 "
        "{%0,%1,%2,%3}, {%4,%5,%6,%7}, {%8,%9}, {%0,%1,%2,%3};"
        : "+f"(c[0]), "+f"(c[1]), "+f"(c[2]), "+f"(c[3])
        : "r"(a[0]), "r"(a[1]), "r"(a[2]), "r"(a[3]), "r"(b0), "r"(b1));
}
__device__ __forceinline__ void cp16u(uint32_t* dstu, const void* src) {
    uint32_t d = sm32(dstu);
    asm volatile("cp.async.cg.shared.global [%0], [%1], 16;" :: "r"(d), "l"(src));
}

// ---- single fused fp32->fp16 weight conversion (one launch) ----
#define F2H_N1 331776
#define F2H_N2 110592
#define F2H_N3 442368
#define F2H_N4 442368
#define F2H_TOT (F2H_N1 + F2H_N2 + F2H_N3 + F2H_N4)
__global__ void k_f2h_all(const float* __restrict__ a, const float* __restrict__ b,
                          const float* __restrict__ c, const float* __restrict__ d,
                          __half* __restrict__ ah, __half* __restrict__ bh,
                          __half* __restrict__ ch, __half* __restrict__ dh) {
    int i = blockIdx.x * 256 + threadIdx.x;
    if (i < F2H_N1) {
        float2 v = ((const float2*)a)[i];
        ((__half2*)ah)[i] = __floats2half2_rn(v.x, v.y);
    } else if (i < F2H_N1 + F2H_N2) {
        int j = i - F2H_N1;
        float2 v = ((const float2*)b)[j];
        ((__half2*)bh)[j] = __floats2half2_rn(v.x, v.y);
    } else if (i < F2H_N1 + F2H_N2 + F2H_N3) {
        int j = i - F2H_N1 - F2H_N2;
        float2 v = ((const float2*)c)[j];
        ((__half2*)ch)[j] = __floats2half2_rn(v.x, v.y);
    } else if (i < F2H_TOT) {
        int j = i - F2H_N1 - F2H_N2 - F2H_N3;
        float2 v = ((const float2*)d)[j];
        ((__half2*)dh)[j] = __floats2half2_rn(v.x, v.y);
    }
}

// ---------------------------------------------------------------
// Fused input transpose + LN1(layer 0). fp16 output only.
// ---------------------------------------------------------------
#define TIN_SMEM_B (192 * 65 * 4)
__global__ __launch_bounds__(256) void k_tin_ln(
    const float* __restrict__ img,
    const float* __restrict__ gam, const float* __restrict__ bet,
    __half* __restrict__ XNh) {
    extern __shared__ float ts[];
    int b = blockIdx.x >> 3, h = blockIdx.x & 7;
    int tid = threadIdx.x;
    const float* ib = img + ((size_t)b * EMB * 8 + h) * 64;
#pragma unroll
    for (int i = 0; i < 48; i++) {
        int idx = tid + i * 256;
        int c = idx >> 6, w = idx & 63;
        ts[c * 65 + w] = ib[(size_t)c * 512 + w];
    }
    __syncthreads();

    int row = tid >> 2, seg = tid & 3;
    float v[48];
    float s = 0.f, sq = 0.f;
#pragma unroll
    for (int j = 0; j < 48; j++) {
        float x = ts[(seg * 48 + j) * 65 + row];
        v[j] = x;
        s += x; sq += x * x;
    }
    s  += __shfl_xor_sync(0xffffffffu, s, 1);
    s  += __shfl_xor_sync(0xffffffffu, s, 2);
    sq += __shfl_xor_sync(0xffffffffu, sq, 1);
    sq += __shfl_xor_sync(0xffffffffu, sq, 2);
    float mu = s * (1.f / 192.f);
    float var = sq * (1.f / 192.f) - mu * mu;
    float rstd = rsqrtf(var + 1e-5f);

    int t = row * 8 + h;
    __half* xnh = XNh + ((size_t)b * SEQ + t) * EMB + seg * 48;
#pragma unroll
    for (int i = 0; i < 12; i++) {
        float4 g4 = *(const float4*)(gam + seg * 48 + i * 4);
        float4 b4 = *(const float4*)(bet + seg * 48 + i * 4);
        float nx = (v[i*4+0] - mu) * rstd * g4.x + b4.x;
        float ny = (v[i*4+1] - mu) * rstd * g4.y + b4.y;
        float nz = (v[i*4+2] - mu) * rstd * g4.z + b4.z;
        float nw = (v[i*4+3] - mu) * rstd * g4.w + b4.w;
        *(__half2*)(xnh + i * 4)     = __floats2half2_rn(nx, ny);
        *(__half2*)(xnh + i * 4 + 2) = __floats2half2_rn(nz, nw);
    }
}

// ---------------------------------------------------------------
// fp16 GEMM with ldmatrix fragments (best config):
// BM=128, BN=64, BK=32; 256 thr (8 warps 4x2); warp tile 32x32; 2 CTAs/SM.
// SCALEQ: scale q-columns (bn<192) by (1/sqrt(32))*log2e for exp2 softmax.
// ---------------------------------------------------------------
#define HPITCH 20
#define HSTAGE_U (128 * HPITCH + 64 * HPITCH)
#define GSMEM_BYTES (3 * HSTAGE_U * 4)

template <int RELU, int SCALEQ, int KT>
__global__ __launch_bounds__(256, 2) void k_gemm_h(
    const __half* __restrict__ A, const __half* __restrict__ W,
    const float* __restrict__ bias, __half* __restrict__ C, int Ntot) {
    extern __shared__ uint32_t shu[];
    const int K = KT * 32;

    const int bm = blockIdx.y * 128;
    const int bn = blockIdx.x * 64;
    const int tid = threadIdx.x;
    const int wid = tid >> 5;
    const int lane = tid & 31;
    const int wm = wid >> 1;
    const int wn = wid & 1;
    const int g  = lane >> 2;
    const int tg = lane & 3;
    const int lrow = lane & 15;
    const int lcol = (lane >> 4) * 4;

    const uint32_t shb = sm32(shu);

    auto load_stage = [&](int kt, int s) {
        uint32_t* as = shu + s * HSTAGE_U;
        uint32_t* bs = as + 128 * HPITCH;
        const __half* Ab = A + (size_t)bm * K + kt * 32;
        const __half* Wb = W + (size_t)bn * K + kt * 32;
#pragma unroll
        for (int i = 0; i < 2; i++) {
            int id = tid + i * 256;
            int r = id >> 2, c = id & 3;
            cp16u(as + r * HPITCH + c * 4, Ab + (size_t)r * K + c * 8);
        }
        {
            int r = tid >> 2, c = tid & 3;
            cp16u(bs + r * HPITCH + c * 4, Wb + (size_t)r * K + c * 8);
        }
        asm volatile("cp.async.commit_group;" ::: "memory");
    };

    float acc[2][4][4];
#pragma unroll
    for (int mm = 0; mm < 2; mm++)
#pragma unroll
        for (int nn = 0; nn < 4; nn++)
#pragma unroll
            for (int r = 0; r < 4; r++) acc[mm][nn][r] = 0.f;

    load_stage(0, 0);
    load_stage(1, 1);

#pragma unroll
    for (int kt = 0; kt < KT; kt++) {
        if (kt + 1 < KT) {
            asm volatile("cp.async.wait_group 1;" ::: "memory");
        } else {
            asm volatile("cp.async.wait_group 0;" ::: "memory");
        }
        __syncthreads();
        if (kt + 2 < KT) load_stage(kt + 2, (kt + 2) % 3);

        const uint32_t ab = shb + ((kt % 3) * HSTAGE_U) * 4;
        const uint32_t bb = ab + 128 * HPITCH * 4;
#pragma unroll
        for (int ks = 0; ks < 2; ks++) {
            uint32_t aa[2][4], bfr[4][2];
#pragma unroll
            for (int mm = 0; mm < 2; mm++)
                ldsm4(aa[mm][0], aa[mm][1], aa[mm][2], aa[mm][3],
                      ab + ((wm * 32 + mm * 16 + lrow) * HPITCH + ks * 8 + lcol) * 4);
#pragma unroll
            for (int np = 0; np < 2; np++) {
                uint32_t r0, r1, r2, r3;
                ldsm4(r0, r1, r2, r3,
                      bb + ((wn * 32 + np * 16 + lrow) * HPITCH + ks * 8 + lcol) * 4);
                bfr[np * 2][0] = r0; bfr[np * 2 + 1][0] = r1;
                bfr[np * 2][1] = r2; bfr[np * 2 + 1][1] = r3;
            }
#pragma unroll
            for (int mm = 0; mm < 2; mm++)
#pragma unroll
                for (int nn = 0; nn < 4; nn++)
                    mma_f16(acc[mm][nn], aa[mm], bfr[nn][0], bfr[nn][1]);
        }
    }

    // (1/sqrt(32)) * log2(e) so attention can use exp2 softmax directly
    const float scl = (SCALEQ && bn < 192) ? 0.25503508748672485f : 1.f;
#pragma unroll
    for (int mm = 0; mm < 2; mm++) {
#pragma unroll
        for (int half = 0; half < 2; half++) {
            int m = bm + wm * 32 + mm * 16 + g + half * 8;
            __half* crow = C + (size_t)m * Ntot + bn;
#pragma unroll
            for (int nn = 0; nn < 4; nn++) {
                int n = wn * 32 + nn * 8 + 2 * tg;
                float vx = (acc[mm][nn][half * 2 + 0] + bias[bn + n]) * scl;
                float vy = (acc[mm][nn][half * 2 + 1] + bias[bn + n + 1]) * scl;
                if (RELU) { vx = fmaxf(vx, 0.f); vy = fmaxf(vy, 0.f); }
                *(__half2*)(crow + n) = __floats2half2_rn(vx, vy);
            }
        }
    }
}

// ---------------------------------------------------------------
// fp16 GEMM (Ntot=192), BM=64 + fp16 residual + fused LN epilogue.
// WRITEX=1 additionally stores pre-LN x (fp32) for k_merge (last layer only).
// ---------------------------------------------------------------
#define LSTAGE_U (64 * HPITCH + 192 * HPITCH)
#define LSMEM_BYTES (3 * LSTAGE_U * 4)
#define XPITCH 196

template <int KT, int WRITEX>
__global__ __launch_bounds__(256, 2) void k_gemm_ln(
    const __half* __restrict__ A, const __half* __restrict__ W,
    const float* __restrict__ bias, const __half* __restrict__ R,
    const float* __restrict__ gam, const float* __restrict__ bet,
    float* __restrict__ X, __half* __restrict__ XNh) {
    extern __shared__ uint32_t shu[];
    const int K = KT * 32;

    const int bm = blockIdx.x * 64;
    const int tid = threadIdx.x;
    const int wid = tid >> 5;
    const int lane = tid & 31;
    const int wm = wid >> 2;
    const int wn = wid & 3;
    const int g  = lane >> 2;
    const int tg = lane & 3;
    const int lrow = lane & 15;
    const int lcol = (lane >> 4) * 4;

    const uint32_t shb = sm32(shu);

    auto load_stage = [&](int kt, int s) {
        uint32_t* as = shu + s * LSTAGE_U;
        uint32_t* bs = as + 64 * HPITCH;
        const __half* Ab = A + (size_t)bm * K + kt * 32;
        const __half* Wb = W + (size_t)kt * 32;
        {
            int r = tid >> 2, c = tid & 3;
            cp16u(as + r * HPITCH + c * 4, Ab + (size_t)r * K + c * 8);
        }
#pragma unroll
        for (int i = 0; i < 3; i++) {
            int id = tid + i * 256;
            int r = id >> 2, c = id & 3;
            cp16u(bs + r * HPITCH + c * 4, Wb + (size_t)r * K + c * 8);
        }
        asm volatile("cp.async.commit_group;" ::: "memory");
    };

    float acc[2][6][4];
#pragma unroll
    for (int mm = 0; mm < 2; mm++)
#pragma unroll
        for (int nn = 0; nn < 6; nn++)
#pragma unroll
            for (int r = 0; r < 4; r++) acc[mm][nn][r] = 0.f;

    load_stage(0, 0);
    load_stage(1, 1);

#pragma unroll
    for (int kt = 0; kt < KT; kt++) {
        if (kt + 1 < KT) {
            asm volatile("cp.async.wait_group 1;" ::: "memory");
        } else {
            asm volatile("cp.async.wait_group 0;" ::: "memory");
        }
        __syncthreads();
        if (kt + 2 < KT) load_stage(kt + 2, (kt + 2) % 3);

        const uint32_t ab = shb + ((kt % 3) * LSTAGE_U) * 4;
        const uint32_t bb = ab + 64 * HPITCH * 4;
#pragma unroll
        for (int ks = 0; ks < 2; ks++) {
            uint32_t aa[2][4], bfr[6][2];
#pragma unroll
            for (int mm = 0; mm < 2; mm++)
                ldsm4(aa[mm][0], aa[mm][1], aa[mm][2], aa[mm][3],
                      ab + ((wm * 32 + mm * 16 + lrow) * HPITCH + ks * 8 + lcol) * 4);
#pragma unroll
            for (int np = 0; np < 3; np++) {
                uint32_t r0, r1, r2, r3;
                ldsm4(r0, r1, r2, r3,
                      bb + ((wn * 48 + np * 16 + lrow) * HPITCH + ks * 8 + lcol) * 4);
                bfr[np * 2][0] = r0; bfr[np * 2 + 1][0] = r1;
                bfr[np * 2][1] = r2; bfr[np * 2 + 1][1] = r3;
            }
#pragma unroll
            for (int mm = 0; mm < 2; mm++)
#pragma unroll
                for (int nn = 0; nn < 6; nn++)
                    mma_f16(acc[mm][nn], aa[mm], bfr[nn][0], bfr[nn][1]);
        }
    }

    __syncthreads();
    float* xbuf = (float*)shu;
#pragma unroll
    for (int mm = 0; mm < 2; mm++) {
#pragma unroll
        for (int half = 0; half < 2; half++) {
            int lr = wm * 32 + mm * 16 + g + half * 8;
            const __half* rrow = R + (size_t)(bm + lr) * EMB;
#pragma unroll
            for (int nn = 0; nn < 6; nn++) {
                int n = wn * 48 + nn * 8 + 2 * tg;
                float2 r2 = __half22float2(*(const __half2*)(rrow + n));
                xbuf[lr * XPITCH + n]     = acc[mm][nn][half * 2 + 0] + bias[n]     + r2.x;
                xbuf[lr * XPITCH + n + 1] = acc[mm][nn][half * 2 + 1] + bias[n + 1] + r2.y;
            }
        }
    }
    __syncthreads();

    {
        int row = tid >> 2, seg = tid & 3;
        const float* xr = xbuf + row * XPITCH + seg * 48;
        float s = 0.f, sq = 0.f;
        float v[48];
#pragma unroll
        for (int i = 0; i < 12; i++) {
            float4 x4 = *(const float4*)(xr + i * 4);
            v[i * 4 + 0] = x4.x; v[i * 4 + 1] = x4.y;
            v[i * 4 + 2] = x4.z; v[i * 4 + 3] = x4.w;
            s += x4.x + x4.y + x4.z + x4.w;
            sq += x4.x * x4.x + x4.y * x4.y + x4.z * x4.z + x4.w * x4.w;
        }
        s  += __shfl_xor_sync(0xffffffffu, s, 1);
        s  += __shfl_xor_sync(0xffffffffu, s, 2);
        sq += __shfl_xor_sync(0xffffffffu, sq, 1);
        sq += __shfl_xor_sync(0xffffffffu, sq, 2);
        float mu = s * (1.f / 192.f);
        float var = sq * (1.f / 192.f) - mu * mu;
        float rstd = rsqrtf(var + 1e-5f);
        float* xo   = X   + (size_t)(bm + row) * EMB + seg * 48;
        __half* xnh = XNh + (size_t)(bm + row) * EMB + seg * 48;
#pragma unroll
        for (int i = 0; i < 12; i++) {
            float4 g4 = *(const float4*)(gam + seg * 48 + i * 4);
            float4 b4 = *(const float4*)(bet + seg * 48 + i * 4);
            float4 xv = { v[i*4+0], v[i*4+1], v[i*4+2], v[i*4+3] };
            if (WRITEX) *(float4*)(xo + i * 4) = xv;
            float nx = (xv.x - mu) * rstd * g4.x + b4.x;
            float ny = (xv.y - mu) * rstd * g4.y + b4.y;
            float nz = (xv.z - mu) * rstd * g4.z + b4.z;
            float nw = (xv.w - mu) * rstd * g4.w + b4.w;
            *(__half2*)(xnh + i * 4)     = __floats2half2_rn(nx, ny);
            *(__half2*)(xnh + i * 4 + 2) = __floats2half2_rn(nz, nw);
        }
    }
}

// ---------------------------------------------------------------
// Full-fp16 flash attention; q pre-scaled by (1/sqrt32)*log2e -> exp2 softmax.
// Single barrier per k-tile (pre-store barrier proven redundant).
// ---------------------------------------------------------------
#define QSU (128 * HPITCH)
#define KSU (64 * HPITCH)
#define VTU (32 * 36)
#define PBU (16 * 36)
#define ATTN_U (QSU + 2 * KSU + 2 * VTU + 8 * PBU)
#define ATTN_SMEM_B (ATTN_U * 4)

__global__ __launch_bounds__(256, 2) void k_attn_tc(
    const __half* __restrict__ qkv, __half* __restrict__ out, int local) {
    extern __shared__ uint32_t smu[];
    uint32_t* Qsu = smu;
    uint32_t* Ksu = Qsu + QSU;
    uint32_t* Vtu = Ksu + 2 * KSU;
    uint32_t* Pbu = Vtu + 2 * VTU;

    const int qt = blockIdx.x, hh = blockIdx.y, b = blockIdx.z;
    const int tid = threadIdx.x;
    const int wid = tid >> 5;
    const int lane = tid & 31;
    const int g = lane >> 2, tg = lane & 3;
    const int lrow = lane & 15;
    const int lcol = (lane >> 4) * 4;
    const __half* base = qkv + (size_t)b * SEQ * 576;

    const int ltok = tid >> 2, lpart = tid & 3;
    uint4 kf, vf;
    {
        const __half* row = base + (size_t)ltok * 576 + hh * HD + lpart * 8;
        kf = *(const uint4*)(row + EMB);
        vf = *(const uint4*)(row + 2 * EMB);
    }
#pragma unroll
    for (int i = 0; i < 2; i++) {
        int id = tid + i * 256;
        int tok = id >> 2, part = id & 3;
        uint4 qv = *(const uint4*)(base + (size_t)(qt * 128 + tok) * 576 + hh * HD + part * 8);
        *(uint4*)(Qsu + tok * HPITCH + part * 4) = qv;
    }
    {
        *(uint4*)(Ksu + ltok * HPITCH + lpart * 4) = kf;
        __half* vh = (__half*)Vtu;
        const __half* vsrc = (const __half*)&vf;
#pragma unroll
        for (int j = 0; j < 8; j++)
            vh[(lpart * 8 + j) * 72 + ltok] = vsrc[j];
    }
    __syncthreads();

    uint32_t qa[2][4];
    {
        uint32_t qb = sm32(Qsu);
#pragma unroll
        for (int c = 0; c < 2; c++)
            ldsm4(qa[c][0], qa[c][1], qa[c][2], qa[c][3],
                  qb + ((wid * 16 + lrow) * HPITCH + c * 8 + lcol) * 4);
    }

    float oacc[4][4];
#pragma unroll
    for (int nd = 0; nd < 4; nd++)
#pragma unroll
        for (int r = 0; r < 4; r++) oacc[nd][r] = 0.f;
    float m0 = -1e30f, m1 = -1e30f, l0 = 0.f, l1 = 0.f;

    const int qrow_grp = qt * 2 + (wid >= 4 ? 1 : 0);
    const int qw0 = (wid * 16 + g) & 63;
    const int qw1 = (wid * 16 + g + 8) & 63;
    uint32_t* Pw = Pbu + wid * PBU;
    const uint32_t pwb = sm32(Pw);

    for (int kt = 0; kt < 8; kt++) {
        int buf = kt & 1;
        if (kt < 7) {
            const __half* row = base + (size_t)((kt + 1) * 64 + ltok) * 576 + hh * HD + lpart * 8;
            kf = *(const uint4*)(row + EMB);
            vf = *(const uint4*)(row + 2 * EMB);
        }

        float sc[8][4];
#pragma unroll
        for (int n = 0; n < 8; n++)
#pragma unroll
            for (int r = 0; r < 4; r++) sc[n][r] = 0.f;
        {
            uint32_t kb = sm32(Ksu + buf * KSU);
#pragma unroll
            for (int c = 0; c < 2; c++) {
                uint32_t bfr[8][2];
#pragma unroll
                for (int np = 0; np < 4; np++) {
                    uint32_t r0, r1, r2, r3;
                    ldsm4(r0, r1, r2, r3,
                          kb + ((np * 16 + lrow) * HPITCH + c * 8 + lcol) * 4);
                    bfr[np * 2][0] = r0; bfr[np * 2 + 1][0] = r1;
                    bfr[np * 2][1] = r2; bfr[np * 2 + 1][1] = r3;
                }
#pragma unroll
                for (int n = 0; n < 8; n++)
                    mma_f16(sc[n], qa[c], bfr[n][0], bfr[n][1]);
            }
        }

        if (local) {
            int dr = qrow_grp - kt;
            if (dr <= 3 && dr >= -3) {
#pragma unroll
                for (int n = 0; n < 8; n++) {
#pragma unroll
                    for (int j = 0; j < 2; j++) {
                        int col = n * 8 + 2 * tg + j;
                        int d0 = qw0 - col, d1 = qw1 - col;
                        if (d0 <= 5 && d0 >= -5) sc[n][j] = -1e30f;
                        if (d1 <= 5 && d1 >= -5) sc[n][2 + j] = -1e30f;
                    }
                }
            }
        }

        float tm0 = sc[0][0], tm1 = sc[0][2];
#pragma unroll
        for (int n = 0; n < 8; n++) {
            tm0 = fmaxf(tm0, fmaxf(sc[n][0], sc[n][1]));
            tm1 = fmaxf(tm1, fmaxf(sc[n][2], sc[n][3]));
        }
        tm0 = fmaxf(tm0, __shfl_xor_sync(0xffffffffu, tm0, 1));
        tm0 = fmaxf(tm0, __shfl_xor_sync(0xffffffffu, tm0, 2));
        tm1 = fmaxf(tm1, __shfl_xor_sync(0xffffffffu, tm1, 1));
        tm1 = fmaxf(tm1, __shfl_xor_sync(0xffffffffu, tm1, 2));
        float nm0 = fmaxf(m0, tm0), nm1 = fmaxf(m1, tm1);
        float f0 = exp2f(m0 - nm0), f1 = exp2f(m1 - nm1);
        l0 *= f0; l1 *= f1;
#pragma unroll
        for (int nd = 0; nd < 4; nd++) {
            oacc[nd][0] *= f0; oacc[nd][1] *= f0;
            oacc[nd][2] *= f1; oacc[nd][3] *= f1;
        }
#pragma unroll
        for (int n = 0; n < 8; n++) {
            float p0 = exp2f(sc[n][0] - nm0);
            float p1 = exp2f(sc[n][1] - nm0);
            float p2 = exp2f(sc[n][2] - nm1);
            float p3 = exp2f(sc[n][3] - nm1);
            l0 += p0 + p1; l1 += p2 + p3;
            Pw[g * 36 + n * 4 + tg]       = h2u(__floats2half2_rn(p0, p1));
            Pw[(g + 8) * 36 + n * 4 + tg] = h2u(__floats2half2_rn(p2, p3));
        }
        m0 = nm0; m1 = nm1;
        __syncwarp();

        {
            uint32_t vb = sm32(Vtu + buf * VTU);
#pragma unroll
            for (int c = 0; c < 4; c++) {
                uint32_t pa[4];
                ldsm4(pa[0], pa[1], pa[2], pa[3],
                      pwb + (lrow * 36 + c * 8 + lcol) * 4);
                uint32_t vfr[4][2];
#pragma unroll
                for (int np = 0; np < 2; np++) {
                    uint32_t r0, r1, r2, r3;
                    ldsm4(r0, r1, r2, r3,
                          vb + ((np * 16 + lrow) * 36 + c * 8 + lcol) * 4);
                    vfr[np * 2][0] = r0; vfr[np * 2 + 1][0] = r1;
                    vfr[np * 2][1] = r2; vfr[np * 2 + 1][1] = r3;
                }
#pragma unroll
                for (int nd = 0; nd < 4; nd++)
                    mma_f16(oacc[nd], pa, vfr[nd][0], vfr[nd][1]);
            }
        }
        __syncwarp();

        if (kt < 7) {
            // store next tile into the buffer last read at iteration kt-1.
            // Safe without a pre-store barrier: every warp finished reading that
            // buffer before the end-of-iteration barrier of kt-1.
            int nbuf = buf ^ 1;
            *(uint4*)(Ksu + nbuf * KSU + ltok * HPITCH + lpart * 4) = kf;
            __half* vh = (__half*)(Vtu + nbuf * VTU);
            const __half* vsrc = (const __half*)&vf;
#pragma unroll
            for (int j = 0; j < 8; j++)
                vh[(lpart * 8 + j) * 72 + ltok] = vsrc[j];
            __syncthreads();
        }
    }

    l0 += __shfl_xor_sync(0xffffffffu, l0, 1);
    l0 += __shfl_xor_sync(0xffffffffu, l0, 2);
    l1 += __shfl_xor_sync(0xffffffffu, l1, 1);
    l1 += __shfl_xor_sync(0xffffffffu, l1, 2);
    float inv0 = 1.f / l0, inv1 = 1.f / l1;
    int r0 = qt * 128 + wid * 16 + g;
    __half* o0 = out + (size_t)(b * SEQ + r0) * EMB + hh * HD;
    __half* o1 = out + (size_t)(b * SEQ + r0 + 8) * EMB + hh * HD;
#pragma unroll
    for (int nd = 0; nd < 4; nd++) {
        int n = nd * 8 + 2 * tg;
        *(__half2*)(o0 + n) = __floats2half2_rn(oacc[nd][0] * inv0, oacc[nd][1] * inv0);
        *(__half2*)(o1 + n) = __floats2half2_rn(oacc[nd][2] * inv1, oacc[nd][3] * inv1);
    }
}

// ---------------------------------------------------------------
// Merge: conv (3,1) stride (2,1) pad (1,0) + channel LN (shuffle reduce).
// ---------------------------------------------------------------
__global__ __launch_bounds__(256) void k_merge(
    const float* __restrict__ cw, const float* __restrict__ cb,
    const float* __restrict__ mg, const float* __restrict__ mb,
    float* __restrict__ out) {
    int blk = blockIdx.x;
    int wg = blk & 15;
    int ho = (blk >> 4) & 3;
    int b  = blk >> 6;
    int co = threadIdx.x;
    int lane = co & 31, wrp = co >> 5;
    __shared__ float xs[4][3][EMB];
    __shared__ float red[8], red2[8];

    for (int idx = co; idx < 4 * 3 * EMB; idx += 256) {
        int g   = idx / (3 * EMB);
        int rem = idx - g * (3 * EMB);
        int kh  = rem / EMB;
        int ci  = rem - kh * EMB;
        int hh  = 2 * ho - 1 + kh;
        int w   = wg * 4 + g;
        float v = 0.f;
        if (hh >= 0 && hh < 8)
            v = g_x[((size_t)b * SEQ + (w * 8 + hh)) * EMB + ci];
        xs[g][kh][ci] = v;
    }
    __syncthreads();

    float bias = cb[co];
    float acc[4] = {bias, bias, bias, bias};
    const float* wp = cw + (size_t)co * (EMB * 3);
    for (int ci = 0; ci < EMB; ci++) {
        float w0 = wp[ci * 3 + 0], w1 = wp[ci * 3 + 1], w2 = wp[ci * 3 + 2];
#pragma unroll
        for (int g = 0; g < 4; g++)
            acc[g] += xs[g][0][ci] * w0 + xs[g][1][ci] * w1 + xs[g][2][ci] * w2;
    }

    float gm = mg[co], gb = mb[co];
#pragma unroll
    for (int g = 0; g < 4; g++) {
        float s = acc[g], sq = acc[g] * acc[g];
#pragma unroll
        for (int o = 16; o; o >>= 1) {
            s  += __shfl_xor_sync(0xffffffffu, s, o);
            sq += __shfl_xor_sync(0xffffffffu, sq, o);
        }
        if (lane == 0) { red[wrp] = s; red2[wrp] = sq; }
        __syncthreads();
        if (wrp == 0) {
            float a  = lane < 8 ? red[lane]  : 0.f;
            float b2 = lane < 8 ? red2[lane] : 0.f;
#pragma unroll
            for (int o = 4; o; o >>= 1) {
                a  += __shfl_xor_sync(0xffffffffu, a, o);
                b2 += __shfl_xor_sync(0xffffffffu, b2, o);
            }
            if (lane == 0) { red[0] = a; red2[0] = b2; }
        }
        __syncthreads();
        float mu = red[0] * (1.f / 256.f);
        float var = red2[0] * (1.f / 256.f) - mu * mu;
        float rstd = rsqrtf(var + 1e-5f);
        int w = wg * 4 + g;
        out[(((size_t)b * 256 + co) * 4 + ho) * 64 + w] = (acc[g] - mu) * rstd * gm + gb;
        __syncthreads();
    }
}

// ---------------------------------------------------------------
extern "C" void kernel_launch(void* const* d_in, const int* in_sizes, int n_in,
                              void* d_out, int out_size) {
    const float* image = (const float*)d_in[0];
    const float* in_w  = (const float*)d_in[1];
    const float* in_b  = (const float*)d_in[2];
    const float* out_w = (const float*)d_in[3];
    const float* out_b = (const float*)d_in[4];
    const float* ln1_g = (const float*)d_in[5];
    const float* ln1_b = (const float*)d_in[6];
    const float* ln2_g = (const float*)d_in[7];
    const float* ln2_b = (const float*)d_in[8];
    const float* w1    = (const float*)d_in[9];
    const float* b1    = (const float*)d_in[10];
    const float* w2    = (const float*)d_in[11];
    const float* b2    = (const float*)d_in[12];
    const float* convw = (const float*)d_in[13];
    const float* convb = (const float*)d_in[14];
    const float* mlng  = (const float*)d_in[15];
    const float* mlnb  = (const float*)d_in[16];

    float *px;
    __half *pxnh, *pbigh, *pattnh, *pinwh, *poutwh, *pw1h, *pw2h;
    cudaGetSymbolAddress((void**)&px,     g_x);
    cudaGetSymbolAddress((void**)&pxnh,   g_xn_h);
    cudaGetSymbolAddress((void**)&pbigh,  g_big_h);
    cudaGetSymbolAddress((void**)&pattnh, g_attn_h);
    cudaGetSymbolAddress((void**)&pinwh,  g_inw_h);
    cudaGetSymbolAddress((void**)&poutwh, g_outw_h);
    cudaGetSymbolAddress((void**)&pw1h,   g_w1_h);
    cudaGetSymbolAddress((void**)&pw2h,   g_w2_h);

    cudaFuncSetAttribute(k_gemm_h<0, 1, 6>, cudaFuncAttributeMaxDynamicSharedMemorySize, GSMEM_BYTES);
    cudaFuncSetAttribute(k_gemm_h<1, 0, 6>, cudaFuncAttributeMaxDynamicSharedMemorySize, GSMEM_BYTES);
    cudaFuncSetAttribute(k_gemm_ln<6, 0>,  cudaFuncAttributeMaxDynamicSharedMemorySize, LSMEM_BYTES);
    cudaFuncSetAttribute(k_gemm_ln<24, 0>, cudaFuncAttributeMaxDynamicSharedMemorySize, LSMEM_BYTES);
    cudaFuncSetAttribute(k_gemm_ln<24, 1>, cudaFuncAttributeMaxDynamicSharedMemorySize, LSMEM_BYTES);
    cudaFuncSetAttribute(k_attn_tc, cudaFuncAttributeMaxDynamicSharedMemorySize, ATTN_SMEM_B);
    cudaFuncSetAttribute(k_tin_ln,  cudaFuncAttributeMaxDynamicSharedMemorySize, TIN_SMEM_B);

    k_f2h_all<<<(F2H_TOT + 255) / 256, 256>>>(
        in_w, out_w, w1, w2, pinwh, poutwh, pw1h, pw2h);
    k_tin_ln<<<BATCH * 8, 256, TIN_SMEM_B>>>(image, ln1_g, ln1_b, pxnh);

    for (int l = 0; l < 6; l++) {
        int local = (l >= 2);  // LOCAL = (F, F, T, T, T, T)
        // qkv (q columns pre-scaled by (1/sqrt(hd))*log2e)
        k_gemm_h<0, 1, 6><<<dim3(9, MROWS / 128), 256, GSMEM_BYTES>>>(
            pxnh, pinwh + (size_t)l * 576 * EMB, in_b + l * 576, pbigh, 576);
        k_attn_tc<<<dim3(4, NHEAD, BATCH), 256, ATTN_SMEM_B>>>(pbigh, pattnh, local);
        // proj + fp16 residual + LN2
        k_gemm_ln<6, 0><<<MROWS / 64, 256, LSMEM_BYTES>>>(
            pattnh, poutwh + (size_t)l * EMB * EMB, out_b + l * EMB,
            pxnh, ln2_g + l * EMB, ln2_b + l * EMB, px, pxnh);
        k_gemm_h<1, 0, 6><<<dim3(12, MROWS / 128), 256, GSMEM_BYTES>>>(
            pxnh, pw1h + (size_t)l * 768 * EMB, b1 + l * 768, pbigh, 768);
        int ln = (l + 1) % 6;
        // mlp2 + fp16 residual + LN1_{l+1}; only last layer stores fp32 x for merge
        if (l == 5) {
            k_gemm_ln<24, 1><<<MROWS / 64, 256, LSMEM_BYTES>>>(
                pbigh, pw2h + (size_t)l * EMB * 768, b2 + l * EMB,
                pxnh, ln1_g + ln * EMB, ln1_b + ln * EMB, px, pxnh);
        } else {
            k_gemm_ln<24, 0><<<MROWS / 64, 256, LSMEM_BYTES>>>(
                pbigh, pw2h + (size_t)l * EMB * 768, b2 + l * EMB,
                pxnh, ln1_g + ln * EMB, ln1_b + ln * EMB, px, pxnh);
        }
    }

    k_merge<<<4096, 256>>>(convw, convb, mlng, mlnb, (float*)d_out);
}